// round 14
// baseline (speedup 1.0000x reference)
#include <cuda_runtime.h>
#include <cuda_fp16.h>
#include <cstdint>

// TPlanesEnc: B=4, N=131072, P=512, F=32.  M = B*N = 524288 points.
// d_in[0] = coords [B,N,3] fp32; d_in[1] = tplanes [3,P,P,F] fp32;
// d_out = [B,N,3F] fp32.
//
// R13: same structure as R12 (fp16 texture copy + half2 lane-paired fused
// kernel, 4 pts/warp) but the 24 texel loads are asm volatile so ptxas
// cannot interleave them with consumption (R12 compiled to regs=32 =>
// loads issued in small waves, realized MLP ~10). Forcing the full batch
// trades occupancy (more regs) for 2x in-flight loads per warp.

#define PS 512
#define FD 32
#define TEXN (3 * PS * PS * FD)   // 25,165,824 elements

__device__ __half g_tex[TEXN];

__device__ __forceinline__ void stg_streaming2(float* p, float a, float b) {
    asm volatile("st.global.cs.v2.f32 [%0], {%1, %2};"
                 :: "l"(p), "f"(a), "f"(b) : "memory");
}

__device__ __forceinline__ uint32_t ldg_nc_b32(const char* p) {
    uint32_t v;
    asm volatile("ld.global.nc.b32 %0, [%1];" : "=r"(v) : "l"(p));
    return v;
}

// ---- Pass 1: fp32 -> fp16 conversion, 8 elems/thread, vectorized ----------
__global__ __launch_bounds__(256)
void convert_kernel(const float* __restrict__ tpl)
{
    const int i = blockIdx.x * blockDim.x + threadIdx.x;   // group of 8
    const int base = i * 8;
    if (base >= TEXN) return;
    const float4 a = __ldcs(reinterpret_cast<const float4*>(tpl + base));
    const float4 b = __ldcs(reinterpret_cast<const float4*>(tpl + base + 4));
    __half2 h0 = __floats2half2_rn(a.x, a.y);
    __half2 h1 = __floats2half2_rn(a.z, a.w);
    __half2 h2 = __floats2half2_rn(b.x, b.y);
    __half2 h3 = __floats2half2_rn(b.z, b.w);
    uint4 pack;
    pack.x = *reinterpret_cast<uint32_t*>(&h0);
    pack.y = *reinterpret_cast<uint32_t*>(&h1);
    pack.z = *reinterpret_cast<uint32_t*>(&h2);
    pack.w = *reinterpret_cast<uint32_t*>(&h3);
    *reinterpret_cast<uint4*>(g_tex + base) = pack;
}

// ---- Pass 2: fused triplane bilerp, half2 lane-paired ---------------------
// Warp handles 4 points as 2 pairs. Within a pair: lanes 0-15 -> point A,
// lanes 16-31 -> point B; lane covers channels (2c, 2c+1), c = lane & 15.
__global__ __launch_bounds__(256)
void tplanes_kernel(const float* __restrict__ coords,
                    float* __restrict__ out,
                    int M)
{
    const int gtid  = blockIdx.x * blockDim.x + threadIdx.x;
    const int warp  = gtid >> 5;
    const int lane  = threadIdx.x & 31;
    const int half  = lane >> 4;       // which point of the pair
    const int c     = lane & 15;       // channel-pair index
    const int pbase = warp * 4;
    if (pbase >= M) return;

    // One coalesced coord fetch for 4 points (12 floats), spread by shuffle.
    float cval = 0.0f;
    if (lane < 12) cval = __ldg(&coords[(size_t)pbase * 3 + lane]);

    // plane 0 samples (u=x, v=y); plane 1 (u=x, v=z); plane 2 (u=z, v=y)
    uint32_t off[24];          // element offsets into g_tex (per-lane point)
    float fu[6], fv[6];

#pragma unroll
    for (int g = 0; g < 2; g++) {
        const int pt = g * 2 + half;   // this lane's point within the warp
        int i0[3], i1[3];
        float fr[3];
#pragma unroll
        for (int a = 0; a < 3; a++) {
            const float cc = __shfl_sync(0xffffffffu, cval, pt * 3 + a);
            float x = (cc * 0.5f + 0.5f) * (float)PS - 0.5f;
            x = fminf(fmaxf(x, 0.0f), (float)(PS - 1));
            const float x0f = floorf(x);
            const int xi0 = (int)x0f;
            i0[a] = xi0;
            i1[a] = min(xi0 + 1, PS - 1);
            fr[a] = x - x0f;
        }

        const int uax[3] = {0, 0, 2};
        const int vax[3] = {1, 2, 1};
#pragma unroll
        for (int p = 0; p < 3; p++) {
            const uint32_t pb = (uint32_t)p * PS * PS * FD;
            const uint32_t r0 = pb + (uint32_t)i0[vax[p]] * (PS * FD);
            const uint32_t r1 = pb + (uint32_t)i1[vax[p]] * (PS * FD);
            const uint32_t c0 = (uint32_t)i0[uax[p]] * FD;
            const uint32_t c1 = (uint32_t)i1[uax[p]] * FD;
            off[g * 12 + p * 4 + 0] = r0 + c0;
            off[g * 12 + p * 4 + 1] = r0 + c1;
            off[g * 12 + p * 4 + 2] = r1 + c0;
            off[g * 12 + p * 4 + 3] = r1 + c1;
            fu[g * 3 + p] = fr[uax[p]];
            fv[g * 3 + p] = fr[vax[p]];
        }
    }

    // Issue ALL 24 texel loads back-to-back (asm volatile: not interleavable).
    // Each instruction: 16 lanes x 4B on each of two 64B texel rows -> 128 B.
    const char* tb = reinterpret_cast<const char*>(g_tex) + (uint32_t)c * 4u;
    uint32_t texb[24];
#pragma unroll
    for (int i = 0; i < 24; i++)
        texb[i] = ldg_nc_b32(tb + (size_t)off[i] * 2u);

#pragma unroll
    for (int g = 0; g < 2; g++) {
        float* op = out + (size_t)(pbase + g * 2 + half) * (3 * FD) + 2 * c;
#pragma unroll
        for (int p = 0; p < 3; p++) {
            const float2 f00 = __half22float2(*reinterpret_cast<__half2*>(&texb[g * 12 + p * 4 + 0]));
            const float2 f01 = __half22float2(*reinterpret_cast<__half2*>(&texb[g * 12 + p * 4 + 1]));
            const float2 f10 = __half22float2(*reinterpret_cast<__half2*>(&texb[g * 12 + p * 4 + 2]));
            const float2 f11 = __half22float2(*reinterpret_cast<__half2*>(&texb[g * 12 + p * 4 + 3]));
            const float xw = fu[g * 3 + p];
            const float yw = fv[g * 3 + p];
            const float tx = f00.x + (f01.x - f00.x) * xw;
            const float ty = f00.y + (f01.y - f00.y) * xw;
            const float bx = f10.x + (f11.x - f10.x) * xw;
            const float by = f10.y + (f11.y - f10.y) * xw;
            stg_streaming2(op + p * FD,
                           tx + (bx - tx) * yw,
                           ty + (by - ty) * yw);
        }
    }
}

extern "C" void kernel_launch(void* const* d_in, const int* in_sizes, int n_in,
                              void* d_out, int out_size)
{
    const float* coords = (const float*)d_in[0];
    const float* tpl    = (const float*)d_in[1];
    float* out          = (float*)d_out;

    const int M = in_sizes[0] / 3;  // total points = B*N

    const int conv_groups = TEXN / 8;
    convert_kernel<<<(conv_groups + 255) / 256, 256>>>(tpl);

    const int points_per_block = (256 / 32) * 4;  // 32
    const int blocks = (M + points_per_block - 1) / points_per_block;
    tplanes_kernel<<<blocks, 256>>>(coords, out, M);
}

// round 15
// speedup vs baseline: 1.0524x; 1.0524x over previous
#include <cuda_runtime.h>
#include <cuda_fp16.h>
#include <cstdint>

// TPlanesEnc: B=4, N=131072, P=512, F=32.  M = B*N = 524288 points.
// d_in[0] = coords [B,N,3] fp32; d_in[1] = tplanes [3,P,P,F] fp32;
// d_out = [B,N,3F] fp32.
//
// R14: R12 structure (fp16 texture copy + half2 lane-paired fused kernel,
// 4 pts/warp: lanes 0-15 point A / 16-31 point B, lane = channel pair) with
// __launch_bounds__(256, 4) so ptxas targets ~64 regs and hoists the
// 24-load batch itself (R12 compiled to 32 regs -> realized MLP ~10;
// R13's asm-volatile forcing made it worse, not better).

#define PS 512
#define FD 32
#define TEXN (3 * PS * PS * FD)   // 25,165,824 elements

__device__ __half g_tex[TEXN];

__device__ __forceinline__ void stg_streaming2(float* p, float a, float b) {
    asm volatile("st.global.cs.v2.f32 [%0], {%1, %2};"
                 :: "l"(p), "f"(a), "f"(b) : "memory");
}

// ---- Pass 1: fp32 -> fp16 conversion, 8 elems/thread, vectorized ----------
__global__ __launch_bounds__(256)
void convert_kernel(const float* __restrict__ tpl)
{
    const int i = blockIdx.x * blockDim.x + threadIdx.x;   // group of 8
    const int base = i * 8;
    if (base >= TEXN) return;
    const float4 a = __ldcs(reinterpret_cast<const float4*>(tpl + base));
    const float4 b = __ldcs(reinterpret_cast<const float4*>(tpl + base + 4));
    __half2 h0 = __floats2half2_rn(a.x, a.y);
    __half2 h1 = __floats2half2_rn(a.z, a.w);
    __half2 h2 = __floats2half2_rn(b.x, b.y);
    __half2 h3 = __floats2half2_rn(b.z, b.w);
    uint4 pack;
    pack.x = *reinterpret_cast<uint32_t*>(&h0);
    pack.y = *reinterpret_cast<uint32_t*>(&h1);
    pack.z = *reinterpret_cast<uint32_t*>(&h2);
    pack.w = *reinterpret_cast<uint32_t*>(&h3);
    *reinterpret_cast<uint4*>(g_tex + base) = pack;
}

// ---- Pass 2: fused triplane bilerp, half2 lane-paired ---------------------
__global__ __launch_bounds__(256, 4)
void tplanes_kernel(const float* __restrict__ coords,
                    float* __restrict__ out,
                    int M)
{
    const int gtid  = blockIdx.x * blockDim.x + threadIdx.x;
    const int warp  = gtid >> 5;
    const int lane  = threadIdx.x & 31;
    const int half  = lane >> 4;       // which point of the pair
    const int c     = lane & 15;       // channel-pair index
    const int pbase = warp * 4;
    if (pbase >= M) return;

    // One coalesced coord fetch for 4 points (12 floats), spread by shuffle.
    float cval = 0.0f;
    if (lane < 12) cval = __ldg(&coords[(size_t)pbase * 3 + lane]);

    // plane 0 samples (u=x, v=y); plane 1 (u=x, v=z); plane 2 (u=z, v=y)
    uint32_t off[24];          // element offsets into g_tex (per-lane point)
    float fu[6], fv[6];

#pragma unroll
    for (int g = 0; g < 2; g++) {
        const int pt = g * 2 + half;   // this lane's point within the warp
        int i0[3], i1[3];
        float fr[3];
#pragma unroll
        for (int a = 0; a < 3; a++) {
            const float cc = __shfl_sync(0xffffffffu, cval, pt * 3 + a);
            float x = (cc * 0.5f + 0.5f) * (float)PS - 0.5f;
            x = fminf(fmaxf(x, 0.0f), (float)(PS - 1));
            const float x0f = floorf(x);
            const int xi0 = (int)x0f;
            i0[a] = xi0;
            i1[a] = min(xi0 + 1, PS - 1);
            fr[a] = x - x0f;
        }

        const int uax[3] = {0, 0, 2};
        const int vax[3] = {1, 2, 1};
#pragma unroll
        for (int p = 0; p < 3; p++) {
            const uint32_t pb = (uint32_t)p * PS * PS * FD;
            const uint32_t r0 = pb + (uint32_t)i0[vax[p]] * (PS * FD);
            const uint32_t r1 = pb + (uint32_t)i1[vax[p]] * (PS * FD);
            const uint32_t c0 = (uint32_t)i0[uax[p]] * FD;
            const uint32_t c1 = (uint32_t)i1[uax[p]] * FD;
            off[g * 12 + p * 4 + 0] = r0 + c0;
            off[g * 12 + p * 4 + 1] = r0 + c1;
            off[g * 12 + p * 4 + 2] = r1 + c0;
            off[g * 12 + p * 4 + 3] = r1 + c1;
            fu[g * 3 + p] = fr[uax[p]];
            fv[g * 3 + p] = fr[vax[p]];
        }
    }

    // 24 texel loads; with the 64-reg budget ptxas hoists these into one
    // batch. Each instruction: 16 lanes x 4B on two 64B texel rows -> 128 B.
    __half2 tex[24];
#pragma unroll
    for (int i = 0; i < 24; i++)
        tex[i] = __ldg(reinterpret_cast<const __half2*>(g_tex + off[i]) + c);

#pragma unroll
    for (int g = 0; g < 2; g++) {
        float* op = out + (size_t)(pbase + g * 2 + half) * (3 * FD) + 2 * c;
#pragma unroll
        for (int p = 0; p < 3; p++) {
            const float2 f00 = __half22float2(tex[g * 12 + p * 4 + 0]);
            const float2 f01 = __half22float2(tex[g * 12 + p * 4 + 1]);
            const float2 f10 = __half22float2(tex[g * 12 + p * 4 + 2]);
            const float2 f11 = __half22float2(tex[g * 12 + p * 4 + 3]);
            const float xw = fu[g * 3 + p];
            const float yw = fv[g * 3 + p];
            const float tx = f00.x + (f01.x - f00.x) * xw;
            const float ty = f00.y + (f01.y - f00.y) * xw;
            const float bx = f10.x + (f11.x - f10.x) * xw;
            const float by = f10.y + (f11.y - f10.y) * xw;
            stg_streaming2(op + p * FD,
                           tx + (bx - tx) * yw,
                           ty + (by - ty) * yw);
        }
    }
}

extern "C" void kernel_launch(void* const* d_in, const int* in_sizes, int n_in,
                              void* d_out, int out_size)
{
    const float* coords = (const float*)d_in[0];
    const float* tpl    = (const float*)d_in[1];
    float* out          = (float*)d_out;

    const int M = in_sizes[0] / 3;  // total points = B*N

    const int conv_groups = TEXN / 8;
    convert_kernel<<<(conv_groups + 255) / 256, 256>>>(tpl);

    const int points_per_block = (256 / 32) * 4;  // 32
    const int blocks = (M + points_per_block - 1) / points_per_block;
    tplanes_kernel<<<blocks, 256>>>(coords, out, M);
}

// round 16
// speedup vs baseline: 1.1329x; 1.0764x over previous
#include <cuda_runtime.h>
#include <cuda_fp16.h>
#include <cstdint>

// TPlanesEnc: B=4, N=131072, P=512, F=32.  M = B*N = 524288 points.
// d_in[0] = coords [B,N,3] fp32; d_in[1] = tplanes [3,P,P,F] fp32;
// d_out = [B,N,3F] fp32.
//
// R15: fp16 texture copy + wide-load main kernel. 8 lanes per point
// (4 pts/warp); each lane loads 16 B (v4) so one instruction covers the
// contiguous (u0,u1) 128 B row chunk of 4 points = 512 B fully used.
// Per point: 6 loads + 3 stores (was 18+6). v-lerp in fp32 per lane,
// u-lerp = weighted butterfly sum between u0/u1 half-lanes (4 shfl).
// Clamp edge exact: u0=511 => fx==0, u1 chunk weight 0 (data finite).

#define PS 512
#define FD 32
#define TEXN (3 * PS * PS * FD)   // 25,165,824 elements

__device__ __half g_tex[TEXN + 32];   // +64B zero pad for edge reads

__device__ __forceinline__ void stg_cs_v4(float* p, float a, float b,
                                          float c, float d) {
    asm volatile("st.global.cs.v4.f32 [%0], {%1, %2, %3, %4};"
                 :: "l"(p), "f"(a), "f"(b), "f"(c), "f"(d) : "memory");
}

// ---- Pass 1: fp32 -> fp16 conversion, 8 elems/thread, vectorized ----------
__global__ __launch_bounds__(256)
void convert_kernel(const float* __restrict__ tpl)
{
    const int i = blockIdx.x * blockDim.x + threadIdx.x;   // group of 8
    const int base = i * 8;
    if (base >= TEXN) return;
    const float4 a = __ldcs(reinterpret_cast<const float4*>(tpl + base));
    const float4 b = __ldcs(reinterpret_cast<const float4*>(tpl + base + 4));
    __half2 h0 = __floats2half2_rn(a.x, a.y);
    __half2 h1 = __floats2half2_rn(a.z, a.w);
    __half2 h2 = __floats2half2_rn(b.x, b.y);
    __half2 h3 = __floats2half2_rn(b.z, b.w);
    uint4 pack;
    pack.x = *reinterpret_cast<uint32_t*>(&h0);
    pack.y = *reinterpret_cast<uint32_t*>(&h1);
    pack.z = *reinterpret_cast<uint32_t*>(&h2);
    pack.w = *reinterpret_cast<uint32_t*>(&h3);
    *reinterpret_cast<uint4*>(g_tex + base) = pack;
}

// ---- Pass 2: fused triplane bilerp, 8 lanes/point, v4 loads ---------------
// lane: pt = lane>>3 (point in group of 4), sub = lane&7,
//       uh = sub>>2 (0: u0 texel half, 1: u1), ck = sub&3 (channels 8ck..+7)
__global__ __launch_bounds__(256, 4)
void tplanes_kernel(const float* __restrict__ coords,
                    float* __restrict__ out,
                    int M)
{
    const int gtid  = blockIdx.x * blockDim.x + threadIdx.x;
    const int warp  = gtid >> 5;
    const int lane  = threadIdx.x & 31;
    const int pbase = warp * 4;
    if (pbase >= M) return;

    const int pt = lane >> 3;
    const int sub = lane & 7;
    const int uh = sub >> 2;
    const int ck = sub & 3;

    // One coalesced coord fetch for 4 points (12 floats), spread by shuffle.
    float cval = 0.0f;
    if (lane < 12) cval = __ldg(&coords[(size_t)pbase * 3 + lane]);

    // Own point's axis params
    int i0[3];
    float fr[3];
#pragma unroll
    for (int a = 0; a < 3; a++) {
        const float cc = __shfl_sync(0xffffffffu, cval, pt * 3 + a);
        float x = (cc * 0.5f + 0.5f) * (float)PS - 0.5f;
        x = fminf(fmaxf(x, 0.0f), (float)(PS - 1));
        const float x0f = floorf(x);
        i0[a] = (int)x0f;
        fr[a] = x - x0f;
    }

    // plane 0 samples (u=x, v=y); plane 1 (u=x, v=z); plane 2 (u=z, v=y)
    const int uax[3] = {0, 0, 2};
    const int vax[3] = {1, 2, 1};

    // 6 wide loads: per plane, rows v0 and v1; 16 B per lane, 128 B per point.
    const char* tb = reinterpret_cast<const char*>(g_tex) + sub * 16;
    uint4 r0[3], r1[3];
#pragma unroll
    for (int p = 0; p < 3; p++) {
        const int u0 = i0[uax[p]];
        const int v0 = i0[vax[p]];
        const int v1 = min(v0 + 1, PS - 1);
        const size_t b0 = ((size_t)((p * PS + v0) * PS + u0)) << 6;  // *64B
        const size_t b1 = ((size_t)((p * PS + v1) * PS + u0)) << 6;
        r0[p] = __ldg(reinterpret_cast<const uint4*>(tb + b0));
        r1[p] = __ldg(reinterpret_cast<const uint4*>(tb + b1));
    }

#pragma unroll
    for (int p = 0; p < 3; p++) {
        const float fx = fr[uax[p]];
        const float fv = fr[vax[p]];
        const float w  = uh ? fx : (1.0f - fx);

        uint32_t t32[4] = {r0[p].x, r0[p].y, r0[p].z, r0[p].w};
        uint32_t b32[4] = {r1[p].x, r1[p].y, r1[p].z, r1[p].w};

        float res[8];
#pragma unroll
        for (int k = 0; k < 4; k++) {
            const float2 t = __half22float2(*reinterpret_cast<__half2*>(&t32[k]));
            const float2 b = __half22float2(*reinterpret_cast<__half2*>(&b32[k]));
            res[2 * k + 0] = (t.x + (b.x - t.x) * fv) * w;
            res[2 * k + 1] = (t.y + (b.y - t.y) * fv) * w;
        }

        // u-lerp: lane uh keeps its 4 store channels, sends the other 4 to
        // its partner (lane ^ 4), adds what it receives.
        float fin[4];
#pragma unroll
        for (int i = 0; i < 4; i++) {
            const float send = uh ? res[i] : res[i + 4];
            const float kept = uh ? res[i + 4] : res[i];
            fin[i] = kept + __shfl_xor_sync(0xffffffffu, send, 4);
        }

        float* op = out + (size_t)(pbase + pt) * 96 + p * 32 + ck * 8 + uh * 4;
        stg_cs_v4(op, fin[0], fin[1], fin[2], fin[3]);
    }
}

extern "C" void kernel_launch(void* const* d_in, const int* in_sizes, int n_in,
                              void* d_out, int out_size)
{
    const float* coords = (const float*)d_in[0];
    const float* tpl    = (const float*)d_in[1];
    float* out          = (float*)d_out;

    const int M = in_sizes[0] / 3;  // total points = B*N

    const int conv_groups = TEXN / 8;
    convert_kernel<<<(conv_groups + 255) / 256, 256>>>(tpl);

    const int points_per_block = (256 / 32) * 4;  // 32
    const int blocks = (M + points_per_block - 1) / points_per_block;
    tplanes_kernel<<<blocks, 256>>>(coords, out, M);
}